// round 3
// baseline (speedup 1.0000x reference)
#include <cuda_runtime.h>

#define NPTS (512 * 512)
#define THREADS 128
#define BLOCKS 456   // 152 SMs * 3 CTAs/SM (smem-limited)

// ---- shared layout (float offsets) ----
// Cp layers 0/1: [i][k][o], k-row stride 34 floats (bank swizzle), i stride 448
#define IST 448
#define KST 34
#define OFF_CP0 0                      // 2*448  = 896
#define OFF_SB0 896                    // 2*32   = 64
#define OFF_CP1 960                    // 32*448 = 14336
#define OFF_SB1 15296                  // 32*32  = 1024
#define OFF_CP2 16320                  // [k][i], stride 33: 13*33=429 -> pad 432
#define OFF_SB2 16752                  // 32
#define SMEM_FLOATS 16784              // 67136 bytes -> 3 CTAs/SM

__device__ __forceinline__ float sigmoidf_(float x) {
    return 1.0f / (1.0f + __expf(-x));
}

// packed dual-fma: acc += a * b (elementwise on float2), via fma.rn.f32x2
__device__ __forceinline__ void ffma2(float2& acc, float2 a, float2 b) {
    asm("{\n\t"
        ".reg .b64 ra, rb, rc;\n\t"
        "mov.b64 ra, {%2,%3};\n\t"
        "mov.b64 rb, {%4,%5};\n\t"
        "mov.b64 rc, {%0,%1};\n\t"
        "fma.rn.f32x2 rc, ra, rb, rc;\n\t"
        "mov.b64 {%0,%1}, rc;\n\t"
        "}"
        : "+f"(acc.x), "+f"(acc.y)
        : "f"(a.x), "f"(a.y), "f"(b.x), "f"(b.y));
}

// uniform cubic B-spline taps at x; clamped indices k0..k3 in [0,12]
__device__ __forceinline__ void spline_taps(float x, float& b0, float& b1, float& b2, float& b3,
                                            int& k0, int& k1, int& k2, int& k3)
{
    float u = x * 10.0f;
    bool inr = (u >= -3.0f) && (u < 13.0f);
    float uc = inr ? u : 0.0f;
    float f  = floorf(uc);
    float t  = uc - f;
    int   m  = (int)f + 3;

    const float C6 = 0.16666667f;
    float t2 = t * t, t3 = t2 * t;
    float omt = 1.0f - t;
    b0 = omt * omt * omt * C6;
    b1 = (3.0f * t3 - 6.0f * t2 + 4.0f) * C6;
    b2 = ((3.0f - 3.0f * t) * t2 + 3.0f * t + 1.0f) * C6;
    b3 = t3 * C6;
    if (!inr)   { b0 = 0.0f; b1 = 0.0f; b2 = 0.0f; b3 = 0.0f; }
    if (m < 3)  b0 = 0.0f;
    if (m < 2)  b1 = 0.0f;
    if (m < 1)  b2 = 0.0f;
    if (m > 12) b3 = 0.0f;
    if (m > 13) b2 = 0.0f;
    if (m > 14) b1 = 0.0f;
    int j = m - 3;
    k0 = max(j, 0);
    k1 = max(min(j + 1, 12), 0);
    k2 = max(min(j + 2, 12), 0);
    k3 = min(j + 3, 12);
}

// wide KAN layer (OUT multiple of 8): weights [i][k][o], float2 loads + f32x2 fma
template <int IN, int OUT>
__device__ __forceinline__ void kan_layer_w(const float* xin, float* xout,
                                            const float* __restrict__ sCp,
                                            const float* __restrict__ sSb)
{
    float2 acc[OUT / 2];
#pragma unroll
    for (int o = 0; o < OUT / 2; o++) acc[o] = make_float2(0.0f, 0.0f);

#pragma unroll 1
    for (int i = 0; i < IN; i++) {
        float x = xin[i];
        float b0, b1, b2, b3; int k0, k1, k2, k3;
        spline_taps(x, b0, b1, b2, b3, k0, k1, k2, k3);
        float base = x * sigmoidf_(x);

        const float* R = sCp + i * IST;
        const float2* r0 = reinterpret_cast<const float2*>(R + k0 * KST);
        const float2* r1 = reinterpret_cast<const float2*>(R + k1 * KST);
        const float2* r2 = reinterpret_cast<const float2*>(R + k2 * KST);
        const float2* r3 = reinterpret_cast<const float2*>(R + k3 * KST);
        const float4* S4 = reinterpret_cast<const float4*>(sSb + i * OUT);

        float2 b0p = make_float2(b0, b0);
        float2 b1p = make_float2(b1, b1);
        float2 b2p = make_float2(b2, b2);
        float2 b3p = make_float2(b3, b3);
        float2 bsp = make_float2(base, base);

#pragma unroll
        for (int q = 0; q < OUT / 4; q++) {
            float4 s = S4[q];                       // uniform addr -> broadcast
            float2 c;
            c = r0[2 * q];     ffma2(acc[2 * q],     b0p, c);
            c = r0[2 * q + 1]; ffma2(acc[2 * q + 1], b0p, c);
            c = r1[2 * q];     ffma2(acc[2 * q],     b1p, c);
            c = r1[2 * q + 1]; ffma2(acc[2 * q + 1], b1p, c);
            c = r2[2 * q];     ffma2(acc[2 * q],     b2p, c);
            c = r2[2 * q + 1]; ffma2(acc[2 * q + 1], b2p, c);
            c = r3[2 * q];     ffma2(acc[2 * q],     b3p, c);
            c = r3[2 * q + 1]; ffma2(acc[2 * q + 1], b3p, c);
            ffma2(acc[2 * q],     bsp, make_float2(s.x, s.y));
            ffma2(acc[2 * q + 1], bsp, make_float2(s.z, s.w));
        }
    }
#pragma unroll
    for (int o = 0; o < OUT / 2; o++) { xout[2 * o] = acc[o].x; xout[2 * o + 1] = acc[o].y; }
}

// final layer (OUT=1): weights [k][i] stride 33 (conflict-free divergent taps)
__device__ __forceinline__ float kan_layer_1(const float* xin,
                                             const float* __restrict__ sCp,
                                             const float* __restrict__ sSb)
{
    float acc = 0.0f;
#pragma unroll 1
    for (int i = 0; i < 32; i++) {
        float x = xin[i];
        float b0, b1, b2, b3; int k0, k1, k2, k3;
        spline_taps(x, b0, b1, b2, b3, k0, k1, k2, k3);
        float base = x * sigmoidf_(x);
        acc = fmaf(sSb[i], base, acc);
        acc = fmaf(b0, sCp[k0 * 33 + i], acc);
        acc = fmaf(b1, sCp[k1 * 33 + i], acc);
        acc = fmaf(b2, sCp[k2 * 33 + i], acc);
        acc = fmaf(b3, sCp[k3 * 33 + i], acc);
    }
    return acc;
}

__global__ void __launch_bounds__(THREADS, 3)
kan_forward(const float* __restrict__ coords,
            const float* __restrict__ coef0, const float* __restrict__ sb0, const float* __restrict__ sp0,
            const float* __restrict__ coef1, const float* __restrict__ sb1, const float* __restrict__ sp1,
            const float* __restrict__ coef2, const float* __restrict__ sb2, const float* __restrict__ sp2,
            const float* __restrict__ dbias,
            float* __restrict__ out)
{
    extern __shared__ float smem[];

    // ---- stage weights: fold sp into coef, transpose to [i][k][o] (layers 0,1) ----
    // layer0: IN=2, OUT=32
    for (int idx = threadIdx.x; idx < 2 * 13 * 32; idx += THREADS) {
        int i = idx / (13 * 32), r = idx % (13 * 32), k = r / 32, o = r % 32;
        smem[OFF_CP0 + i * IST + k * KST + o] = sp0[i * 32 + o] * coef0[(i * 32 + o) * 13 + k];
    }
    // layer1: IN=32, OUT=32
    for (int idx = threadIdx.x; idx < 32 * 13 * 32; idx += THREADS) {
        int i = idx / (13 * 32), r = idx % (13 * 32), k = r / 32, o = r % 32;
        smem[OFF_CP1 + i * IST + k * KST + o] = sp1[i * 32 + o] * coef1[(i * 32 + o) * 13 + k];
    }
    // layer2: IN=32, OUT=1 -> [k][i] stride 33
    for (int idx = threadIdx.x; idx < 13 * 32; idx += THREADS) {
        int k = idx / 32, i = idx % 32;
        smem[OFF_CP2 + k * 33 + i] = sp2[i] * coef2[i * 13 + k];
    }
    for (int idx = threadIdx.x; idx < 64;   idx += THREADS) smem[OFF_SB0 + idx] = sb0[idx];
    for (int idx = threadIdx.x; idx < 1024; idx += THREADS) smem[OFF_SB1 + idx] = sb1[idx];
    for (int idx = threadIdx.x; idx < 32;   idx += THREADS) smem[OFF_SB2 + idx] = sb2[idx];
    __syncthreads();

    float bias = dbias[0];
    int stride = gridDim.x * THREADS;
    for (int p = blockIdx.x * THREADS + threadIdx.x; p < NPTS; p += stride) {
        float2 c = reinterpret_cast<const float2*>(coords)[p];
        float h0[2] = { c.x, c.y };
        float h1[32], h2[32];
        kan_layer_w<2, 32>(h0, h1, smem + OFF_CP0, smem + OFF_SB0);
        kan_layer_w<32, 32>(h1, h2, smem + OFF_CP1, smem + OFF_SB1);
        float lg = kan_layer_1(h2, smem + OFF_CP2, smem + OFF_SB2);
        out[p] = sigmoidf_(lg + bias);
    }
}

extern "C" void kernel_launch(void* const* d_in, const int* in_sizes, int n_in,
                              void* d_out, int out_size)
{
    // order: coords, grid0, coef0, sb0, sp0, grid1, coef1, sb1, sp1, grid2, coef2, sb2, sp2, density_bias
    const float* coords = (const float*)d_in[0];
    const float* coef0  = (const float*)d_in[2];
    const float* sb0    = (const float*)d_in[3];
    const float* sp0    = (const float*)d_in[4];
    const float* coef1  = (const float*)d_in[6];
    const float* sb1    = (const float*)d_in[7];
    const float* sp1    = (const float*)d_in[8];
    const float* coef2  = (const float*)d_in[10];
    const float* sb2    = (const float*)d_in[11];
    const float* sp2    = (const float*)d_in[12];
    const float* dbias  = (const float*)d_in[13];
    float* out = (float*)d_out;

    size_t smem_bytes = SMEM_FLOATS * sizeof(float);
    cudaFuncSetAttribute(kan_forward, cudaFuncAttributeMaxDynamicSharedMemorySize, (int)smem_bytes);
    kan_forward<<<BLOCKS, THREADS, smem_bytes>>>(coords,
                                                 coef0, sb0, sp0,
                                                 coef1, sb1, sp1,
                                                 coef2, sb2, sp2,
                                                 dbias, out);
}